// round 5
// baseline (speedup 1.0000x reference)
#include <cuda_runtime.h>
#include <cuda_fp16.h>
#include <cstdint>

// Problem: B=4, C=256, HW=4096. S = Q^T K per batch; outputs S[:, :1024, :1024] + argmax rows.
#define BATCH   4
#define CDIM    256
#define HWDIM   4096
#define VIS     1024
#define KSPLIT  512            // [hi(256) | lo(256)] halfs per hw-row
#define TILE_M  128
#define TILE_N  256
#define NCHUNKS (HWDIM / TILE_N)        // 16
#define KSTEPS  24                      // per chunk: K_eff=768 in BK=32 steps
#define TOTSTEPS (NCHUNKS * KSTEPS)     // 384
#define STAGE_BYTES 24576               // A 8KB + B 16KB
#define SM_RED  98304                   // after 4 stages
#define SM_TOTAL (SM_RED + 8192)
#define GAP_TAU 0.05f

// Scratch: transposed + fp16 hi/lo split operands (allocation-free device globals).
__device__ __half g_QT[(size_t)BATCH * HWDIM * KSPLIT];
__device__ __half g_KT[(size_t)BATCH * HWDIM * KSPLIT];

#define CP16(dst, src) \
    asm volatile("cp.async.cg.shared.global [%0], [%1], 16;" :: "r"(dst), "l"(src))
#define CP_COMMIT() asm volatile("cp.async.commit_group;" ::: "memory")
#define CP_WAIT2()  asm volatile("cp.async.wait_group 2;" ::: "memory")

__device__ __forceinline__ uint32_t smem_u32(const void* p) {
    uint32_t a;
    asm("{ .reg .u64 t; cvta.to.shared.u64 t, %1; cvt.u32.u64 %0, t; }" : "=r"(a) : "l"(p));
    return a;
}
__device__ __forceinline__ void ldsm4(uint32_t* r, uint32_t addr) {
    asm volatile("ldmatrix.sync.aligned.m8n8.x4.shared.b16 {%0,%1,%2,%3}, [%4];"
                 : "=r"(r[0]), "=r"(r[1]), "=r"(r[2]), "=r"(r[3]) : "r"(addr));
}
__device__ __forceinline__ void mma16816(float* d, const uint32_t* a, const uint32_t* b) {
    asm volatile("mma.sync.aligned.m16n8k16.row.col.f32.f16.f16.f32 "
                 "{%0,%1,%2,%3}, {%4,%5,%6,%7}, {%8,%9}, {%0,%1,%2,%3};"
                 : "+f"(d[0]), "+f"(d[1]), "+f"(d[2]), "+f"(d[3])
                 : "r"(a[0]), "r"(a[1]), "r"(a[2]), "r"(a[3]), "r"(b[0]), "r"(b[1]));
}
// top-2 insert with first-occurrence tie rule (lower index wins on equal value)
__device__ __forceinline__ void top2_ins(float v, int i, float& v1, int& i1, float& v2, int& i2) {
    if (v > v1 || (v == v1 && i < i1)) { v2 = v1; i2 = i1; v1 = v; i1 = i; }
    else if (v > v2 || (v == v2 && i < i2)) { v2 = v; i2 = i; }
}

// ---- Kernel 1: transpose + fp16 hi/lo split ----
__global__ __launch_bounds__(256, 4)
void split_tp(const float* __restrict__ Q, const float* __restrict__ K)
{
    const int bz = blockIdx.z;                   // bit0 = which tensor, bits1.. = batch
    const float* src = ((bz & 1) ? K : Q) + (size_t)(bz >> 1) * CDIM * HWDIM;
    __half* dst = ((bz & 1) ? g_KT : g_QT) + (size_t)(bz >> 1) * HWDIM * KSPLIT;
    __shared__ float t[32][33];
    const int x0 = blockIdx.x * 32;              // hw
    const int y0 = blockIdx.y * 32;              // c
    const int tx = threadIdx.x & 31, ty = threadIdx.x >> 5;
#pragma unroll
    for (int j = 0; j < 4; ++j)
        t[ty + 8 * j][tx] = src[(size_t)(y0 + ty + 8 * j) * HWDIM + x0 + tx];
    __syncthreads();
#pragma unroll
    for (int j = 0; j < 4; ++j) {
        const int hw = x0 + ty + 8 * j;
        const float x = t[tx][ty + 8 * j];
        const __half hi = __float2half_rn(x);
        const __half lo = __float2half_rn(x - __half2float(hi));
        const size_t o = (size_t)hw * KSPLIT + y0 + tx;
        dst[o] = hi;
        dst[o + CDIM] = lo;
    }
}

// one cp.async stage: A 128x32 halfs (8KB), B 256x32 halfs (16KB), swizzled 64B rows.
__device__ __forceinline__ void issue_stage(
    uint32_t smb, int slot, const __half* QTb, const __half* KTb,
    int chunk, int ks, int srcoff, int dst0)
{
    const int seg = ks >> 3, kb = ks & 7;
    const int ca = ((seg == 2) ? CDIM : 0) + kb * 32;   // A: [hi | hi | lo]
    const int cb = ((seg == 1) ? CDIM : 0) + kb * 32;   // B: [hi | lo | hi]
    const uint32_t ab = smb + slot * STAGE_BYTES;
    const uint32_t bb = ab + 8192;
    CP16(ab + dst0, QTb + srcoff + ca);
    const __half* pb = KTb + (size_t)chunk * TILE_N * KSPLIT + srcoff + cb;
    CP16(bb + dst0, pb);
    CP16(bb + dst0 + 8192, pb + (size_t)128 * KSPLIT);
}

// ---- Kernel 2: fp16-split mma.sync GEMM + top2 argmax + exact fixup ----
__global__ __launch_bounds__(512, 1)
void gemm_fp16(const float* __restrict__ Qo, const float* __restrict__ Ko,
               float* __restrict__ Svis, void* __restrict__ Hout, int hmode)
{
    extern __shared__ char smem[];
    const uint32_t smb = smem_u32(smem);
    const int tid = threadIdx.x;
    const int lane = tid & 31, wid = tid >> 5;
    const int wm = wid >> 2, wn = wid & 3;          // warp grid 4(M) x 4(N), tile 32x64
    const int b = blockIdx.y;
    const int q0 = blockIdx.x * TILE_M;

    const __half* QTb = g_QT + ((size_t)(b * HWDIM + q0)) * KSPLIT;
    const __half* KTb = g_KT + (size_t)b * HWDIM * KSPLIT;

    // cp.async mapping: per thread, unit t (A row & B row t>>2) and B row 128+(t>>2).
    const int r0 = tid >> 2, u0 = tid & 3;
    const int srcoff = r0 * KSPLIT + u0 * 8;
    const int dst0 = r0 * 64 + ((u0 ^ ((r0 >> 1) & 3)) * 16);

    // ldmatrix lane geometry
    const int arow = lane & 15;
    const int auk  = (lane >> 4) & 1;
    const int brow = (lane & 7) + ((lane >> 4) & 1) * 8;
    const int buk  = (lane >> 3) & 1;

    int am[2], axor[2];
#pragma unroll
    for (int mt = 0; mt < 2; ++mt) {
        const int m = wm * 32 + mt * 16 + arow;
        am[mt] = m * 64;
        axor[mt] = (m >> 1) & 3;
    }
    int bn[4], bxor[4];
#pragma unroll
    for (int p = 0; p < 4; ++p) {
        const int n = wn * 64 + p * 16 + brow;
        bn[p] = n * 64;
        bxor[p] = (n >> 1) & 3;
    }

    const float NEG_INF = __int_as_float(0xff800000);
    float tv1[4], tv2[4];
    int   ti1[4], ti2[4];
#pragma unroll
    for (int s = 0; s < 4; ++s) { tv1[s] = NEG_INF; tv2[s] = NEG_INF; ti1[s] = 0; ti2[s] = 1; }

    // Prologue: 3 stages in flight
    int pf_chunk = 0, pf_ks = 0;
#pragma unroll
    for (int s = 0; s < 3; ++s) {
        issue_stage(smb, s, QTb, KTb, pf_chunk, pf_ks, srcoff, dst0);
        CP_COMMIT();
        if (++pf_ks == KSTEPS) { pf_ks = 0; ++pf_chunk; }
    }

    int gs = 0;
    const bool visq = (q0 < VIS);

    for (int chunk = 0; chunk < NCHUNKS; ++chunk) {
        float acc[2][8][4];
#pragma unroll
        for (int mt = 0; mt < 2; ++mt)
#pragma unroll
        for (int nt = 0; nt < 8; ++nt)
#pragma unroll
        for (int e = 0; e < 4; ++e) acc[mt][nt][e] = 0.f;

        for (int ks = 0; ks < KSTEPS; ++ks, ++gs) {
            CP_WAIT2();
            __syncthreads();
            const int slot = gs & 3;
            const uint32_t ab = smb + slot * STAGE_BYTES;
            const uint32_t bb = ab + 8192;
#pragma unroll
            for (int k16 = 0; k16 < 2; ++k16) {
                uint32_t af[2][4];
#pragma unroll
                for (int mt = 0; mt < 2; ++mt) {
                    const int u = (k16 * 2 + auk) ^ axor[mt];
                    ldsm4(af[mt], ab + am[mt] + u * 16);
                }
                uint32_t bf[4][4];
#pragma unroll
                for (int p = 0; p < 4; ++p) {
                    const int u = (k16 * 2 + buk) ^ bxor[p];
                    ldsm4(bf[p], bb + bn[p] + u * 16);
                }
#pragma unroll
                for (int mt = 0; mt < 2; ++mt)
#pragma unroll
                for (int nt = 0; nt < 8; ++nt)
                    mma16816(acc[mt][nt], af[mt], &bf[nt >> 1][(nt & 1) * 2]);
            }
            if (gs + 3 < TOTSTEPS) {
                issue_stage(smb, (gs + 3) & 3, QTb, KTb, pf_chunk, pf_ks, srcoff, dst0);
                if (++pf_ks == KSTEPS) { pf_ks = 0; ++pf_chunk; }
            }
            CP_COMMIT();
        }

        // Epilogue: top-2 update + visible-corner store from fragments.
        const int n0 = chunk * TILE_N;
#pragma unroll
        for (int mt = 0; mt < 2; ++mt)
#pragma unroll
        for (int nt = 0; nt < 8; ++nt) {
            const int nb = n0 + wn * 64 + nt * 8 + (lane & 3) * 2;
#pragma unroll
            for (int h = 0; h < 2; ++h) {
                const int s = mt * 2 + h;
#pragma unroll
                for (int j = 0; j < 2; ++j)
                    top2_ins(acc[mt][nt][h * 2 + j], nb + j, tv1[s], ti1[s], tv2[s], ti2[s]);
            }
        }
        if (visq && n0 < VIS) {
#pragma unroll
            for (int mt = 0; mt < 2; ++mt)
#pragma unroll
            for (int h = 0; h < 2; ++h) {
                const int q = q0 + wm * 32 + mt * 16 + (lane >> 2) + h * 8;
                float* row = Svis + ((size_t)(b * VIS + q)) * VIS;
#pragma unroll
                for (int nt = 0; nt < 8; ++nt) {
                    const int n = n0 + wn * 64 + nt * 8 + (lane & 3) * 2;
                    *(float2*)(row + n) = make_float2(acc[mt][nt][h * 2], acc[mt][nt][h * 2 + 1]);
                }
            }
        }
    }

    // Lane reduction: lanes sharing a row differ in bits 0-1.
#pragma unroll
    for (int s = 0; s < 4; ++s) {
#pragma unroll
        for (int off = 1; off <= 2; off <<= 1) {
            const float ov1 = __shfl_xor_sync(0xffffffffu, tv1[s], off);
            const int   oi1 = __shfl_xor_sync(0xffffffffu, ti1[s], off);
            const float ov2 = __shfl_xor_sync(0xffffffffu, tv2[s], off);
            const int   oi2 = __shfl_xor_sync(0xffffffffu, ti2[s], off);
            top2_ins(ov1, oi1, tv1[s], ti1[s], tv2[s], ti2[s]);
            top2_ins(ov2, oi2, tv1[s], ti1[s], tv2[s], ti2[s]);
        }
    }
    // Cross-warp (4 wn groups) via smem: [wn][128] per field.
    float* mv1 = (float*)(smem + SM_RED);
    int*   mi1 = (int*)(smem + SM_RED + 2048);
    float* mv2 = (float*)(smem + SM_RED + 4096);
    int*   mi2 = (int*)(smem + SM_RED + 6144);
    __syncthreads();
    if ((lane & 3) == 0) {
#pragma unroll
        for (int s = 0; s < 4; ++s) {
            const int row = wm * 32 + (s >> 1) * 16 + (s & 1) * 8 + (lane >> 2);
            mv1[wn * 128 + row] = tv1[s];
            mi1[wn * 128 + row] = ti1[s];
            mv2[wn * 128 + row] = tv2[s];
            mi2[wn * 128 + row] = ti2[s];
        }
    }
    __syncthreads();
    if (tid < 128) {
        float v1 = mv1[tid], v2 = mv2[tid];
        int   i1 = mi1[tid], i2 = mi2[tid];
#pragma unroll
        for (int w = 1; w < 4; ++w) {
            top2_ins(mv1[w * 128 + tid], mi1[w * 128 + tid], v1, i1, v2, i2);
            top2_ins(mv2[w * 128 + tid], mi2[w * 128 + tid], v1, i1, v2, i2);
        }
        int idx = i1;
        if (v1 - v2 < GAP_TAU) {
            // Exact fp64 re-score of the two candidates from original fp32 data.
            const float* Qc = Qo + (size_t)b * CDIM * HWDIM + (q0 + tid);
            const float* Ka = Ko + (size_t)b * CDIM * HWDIM + i1;
            const float* Kb2 = Ko + (size_t)b * CDIM * HWDIM + i2;
            double e1 = 0.0, e2 = 0.0;
            for (int c = 0; c < CDIM; ++c) {
                const double qv = (double)Qc[(size_t)c * HWDIM];
                e1 += qv * (double)Ka[(size_t)c * HWDIM];
                e2 += qv * (double)Kb2[(size_t)c * HWDIM];
            }
            if (e2 > e1 || (e2 == e1 && i2 < i1)) idx = i2;
        }
        const size_t hq = (size_t)b * HWDIM + q0 + tid;
        if (hmode == 1) ((long long*)Hout)[hq] = (long long)idx;
        else            ((float*)Hout)[hq] = (float)idx;
    }
}

extern "C" void kernel_launch(void* const* d_in, const int* in_sizes, int n_in,
                              void* d_out, int out_size)
{
    const float* Q = (const float*)d_in[0];
    const float* K = (const float*)d_in[1];
    // V unused by reference outputs.

    float* Svis = (float*)d_out;
    const size_t svis_elems = (size_t)BATCH * VIS * VIS;

    int hmode;
    void* hptr;
    if (out_size == 4227072) {
        hmode = 1;
        hptr = (void*)((char*)d_out + svis_elems * sizeof(float));
    } else {
        hmode = 0;
        hptr = (void*)((float*)d_out + svis_elems);
    }

    static int attr_done = 0;
    if (!attr_done) {
        cudaFuncSetAttribute(gemm_fp16, cudaFuncAttributeMaxDynamicSharedMemorySize, SM_TOTAL);
        attr_done = 1;
    }

    split_tp<<<dim3(HWDIM / 32, CDIM / 32, 2 * BATCH), 256>>>(Q, K);
    gemm_fp16<<<dim3(HWDIM / TILE_M, BATCH), 512, SM_TOTAL>>>(Q, K, Svis, hptr, hmode);
}

// round 6
// speedup vs baseline: 1.0040x; 1.0040x over previous
#include <cuda_runtime.h>
#include <cuda_fp16.h>
#include <cstdint>

// Problem: B=4, C=256, HW=4096. S = Q^T K per batch; outputs S[:, :1024, :1024] + argmax rows.
// 2-segment fp16 split: S ~= (Q_hi + Q_lo) * K_hi. Value err std ~2.3e-3 abs (~1.4e-4 norm);
// argmax exactness restored by fp64 re-score of top-2 candidates when gap < GAP_TAU.
#define BATCH   4
#define CDIM    256
#define HWDIM   4096
#define VIS     1024
#define KSPLIT  512            // Q scratch: [hi(256) | lo(256)] per hw-row
#define TILE_M  128
#define TILE_N  128
#define NCHUNKS (HWDIM / TILE_N)        // 32
#define KSTEPS  16                      // 2 segs x 8 k-blocks of 32
#define TOTSTEPS (NCHUNKS * KSTEPS)     // 512
#define STAGE_BYTES 16384               // A 8KB + B 8KB
#define SM_RED  65536                   // after 4 stages
#define SM_TOTAL (SM_RED + 8192)
#define GAP_TAU 0.05f

// Scratch (allocation-free device globals).
__device__ __half g_QT[(size_t)BATCH * HWDIM * KSPLIT];   // hi|lo
__device__ __half g_KT[(size_t)BATCH * HWDIM * CDIM];     // hi only

#define CP16(dst, src) \
    asm volatile("cp.async.cg.shared.global [%0], [%1], 16;" :: "r"(dst), "l"(src))
#define CP_COMMIT() asm volatile("cp.async.commit_group;" ::: "memory")
#define CP_WAIT2()  asm volatile("cp.async.wait_group 2;" ::: "memory")

__device__ __forceinline__ uint32_t smem_u32(const void* p) {
    uint32_t a;
    asm("{ .reg .u64 t; cvta.to.shared.u64 t, %1; cvt.u32.u64 %0, t; }" : "=r"(a) : "l"(p));
    return a;
}
__device__ __forceinline__ void ldsm4(uint32_t* r, uint32_t addr) {
    asm volatile("ldmatrix.sync.aligned.m8n8.x4.shared.b16 {%0,%1,%2,%3}, [%4];"
                 : "=r"(r[0]), "=r"(r[1]), "=r"(r[2]), "=r"(r[3]) : "r"(addr));
}
__device__ __forceinline__ void mma16816(float* d, const uint32_t* a, const uint32_t* b) {
    asm volatile("mma.sync.aligned.m16n8k16.row.col.f32.f16.f16.f32 "
                 "{%0,%1,%2,%3}, {%4,%5,%6,%7}, {%8,%9}, {%0,%1,%2,%3};"
                 : "+f"(d[0]), "+f"(d[1]), "+f"(d[2]), "+f"(d[3])
                 : "r"(a[0]), "r"(a[1]), "r"(a[2]), "r"(a[3]), "r"(b[0]), "r"(b[1]));
}
__device__ __forceinline__ void top2_ins(float v, int i, float& v1, int& i1, float& v2, int& i2) {
    if (v > v1 || (v == v1 && i < i1)) { v2 = v1; i2 = i1; v1 = v; i1 = i; }
    else if (v > v2 || (v == v2 && i < i2)) { v2 = v; i2 = i; }
}

// ---- Kernel 1: transpose + fp16 split (Q: hi+lo, K: hi only) ----
__global__ __launch_bounds__(256, 4)
void split_tp(const float* __restrict__ Q, const float* __restrict__ K)
{
    const int bz = blockIdx.z;                   // bit0 = which tensor, bits1.. = batch
    const bool isK = (bz & 1);
    const float* src = (isK ? K : Q) + (size_t)(bz >> 1) * CDIM * HWDIM;
    __shared__ float t[32][33];
    const int x0 = blockIdx.x * 32;              // hw
    const int y0 = blockIdx.y * 32;              // c
    const int tx = threadIdx.x & 31, ty = threadIdx.x >> 5;
#pragma unroll
    for (int j = 0; j < 4; ++j)
        t[ty + 8 * j][tx] = src[(size_t)(y0 + ty + 8 * j) * HWDIM + x0 + tx];
    __syncthreads();
    if (isK) {
        __half* dst = g_KT + (size_t)(bz >> 1) * HWDIM * CDIM;
#pragma unroll
        for (int j = 0; j < 4; ++j) {
            const int hw = x0 + ty + 8 * j;
            dst[(size_t)hw * CDIM + y0 + tx] = __float2half_rn(t[tx][ty + 8 * j]);
        }
    } else {
        __half* dst = g_QT + (size_t)(bz >> 1) * HWDIM * KSPLIT;
#pragma unroll
        for (int j = 0; j < 4; ++j) {
            const int hw = x0 + ty + 8 * j;
            const float x = t[tx][ty + 8 * j];
            const __half hi = __float2half_rn(x);
            const __half lo = __float2half_rn(x - __half2float(hi));
            const size_t o = (size_t)hw * KSPLIT + y0 + tx;
            dst[o] = hi;
            dst[o + CDIM] = lo;
        }
    }
}

// one cp.async stage: A 128x32 halfs (Q hi|lo), B 128x32 halfs (K hi), swizzled 64B rows.
__device__ __forceinline__ void issue_stage(
    uint32_t smb, int slot, const __half* QTb, const __half* KTb,
    int chunk, int ks, int soffA, int soffB, int dst0)
{
    const int kb32 = (ks & 7) * 32;
    const int ca = ((ks >> 3) ? CDIM : 0) + kb32;    // seg0: Q-hi, seg1: Q-lo
    const uint32_t ab = smb + slot * STAGE_BYTES;
    const uint32_t bb = ab + 8192;
    const __half* pa = QTb + soffA + ca;
    CP16(ab + dst0, pa);
    CP16(ab + dst0 + 4096, pa + 64 * KSPLIT);
    const __half* pb = KTb + (size_t)chunk * TILE_N * CDIM + soffB + kb32;
    CP16(bb + dst0, pb);
    CP16(bb + dst0 + 4096, pb + 64 * CDIM);
}

// ---- Kernel 2: fp16-split mma.sync GEMM + top2 argmax + exact fixup ----
__global__ __launch_bounds__(256, 1)
void gemm_fp16(const float* __restrict__ Qo, const float* __restrict__ Ko,
               float* __restrict__ Svis, void* __restrict__ Hout, int hmode)
{
    extern __shared__ char smem[];
    const uint32_t smb = smem_u32(smem);
    const int tid = threadIdx.x;
    const int lane = tid & 31, wid = tid >> 5;
    const int wm = wid >> 2, wn = wid & 3;          // warp grid 2(M) x 4(N), tile 64x32
    const int b = blockIdx.y;
    const int q0 = blockIdx.x * TILE_M;

    const __half* QTb = g_QT + ((size_t)(b * HWDIM + q0)) * KSPLIT;
    const __half* KTb = g_KT + (size_t)b * HWDIM * CDIM;

    // cp.async mapping: thread covers row tid>>2 and row 64+(tid>>2), 16B unit tid&3.
    const int r0 = tid >> 2, u0 = tid & 3;
    const int soffA = r0 * KSPLIT + u0 * 8;
    const int soffB = r0 * CDIM + u0 * 8;
    const int dst0 = r0 * 64 + ((u0 ^ ((r0 >> 1) & 3)) * 16);

    // ldmatrix lane geometry
    const int arow = lane & 15;
    const int auk  = (lane >> 4) & 1;
    const int brow = (lane & 7) + ((lane >> 4) & 1) * 8;
    const int buk  = (lane >> 3) & 1;

    int am[4], axor[4];
#pragma unroll
    for (int mt = 0; mt < 4; ++mt) {
        const int m = wm * 64 + mt * 16 + arow;
        am[mt] = m * 64;
        axor[mt] = (m >> 1) & 3;
    }
    int bn[2], bxor[2];
#pragma unroll
    for (int p = 0; p < 2; ++p) {
        const int n = wn * 32 + p * 16 + brow;
        bn[p] = n * 64;
        bxor[p] = (n >> 1) & 3;
    }

    const float NEG_INF = __int_as_float(0xff800000);
    float tv1[8], tv2[8];
    int   ti1[8], ti2[8];
#pragma unroll
    for (int s = 0; s < 8; ++s) { tv1[s] = NEG_INF; tv2[s] = NEG_INF; ti1[s] = 0; ti2[s] = 1; }

    // Prologue: 3 stages in flight
    int pf_chunk = 0, pf_ks = 0;
#pragma unroll
    for (int s = 0; s < 3; ++s) {
        issue_stage(smb, s, QTb, KTb, pf_chunk, pf_ks, soffA, soffB, dst0);
        CP_COMMIT();
        if (++pf_ks == KSTEPS) { pf_ks = 0; ++pf_chunk; }
    }

    int gs = 0;
    const bool visq = (q0 < VIS);

    for (int chunk = 0; chunk < NCHUNKS; ++chunk) {
        float acc[4][4][4];
#pragma unroll
        for (int mt = 0; mt < 4; ++mt)
#pragma unroll
        for (int nt = 0; nt < 4; ++nt)
#pragma unroll
        for (int e = 0; e < 4; ++e) acc[mt][nt][e] = 0.f;

        for (int ks = 0; ks < KSTEPS; ++ks, ++gs) {
            CP_WAIT2();
            __syncthreads();
            const int slot = gs & 3;
            const uint32_t ab = smb + slot * STAGE_BYTES;
            const uint32_t bb = ab + 8192;
#pragma unroll
            for (int k16 = 0; k16 < 2; ++k16) {
                uint32_t af[4][4];
#pragma unroll
                for (int mt = 0; mt < 4; ++mt) {
                    const int u = (k16 * 2 + auk) ^ axor[mt];
                    ldsm4(af[mt], ab + am[mt] + u * 16);
                }
                uint32_t bf[2][4];
#pragma unroll
                for (int p = 0; p < 2; ++p) {
                    const int u = (k16 * 2 + buk) ^ bxor[p];
                    ldsm4(bf[p], bb + bn[p] + u * 16);
                }
#pragma unroll
                for (int mt = 0; mt < 4; ++mt)
#pragma unroll
                for (int nt = 0; nt < 4; ++nt)
                    mma16816(acc[mt][nt], af[mt], &bf[nt >> 1][(nt & 1) * 2]);
            }
            if (gs + 3 < TOTSTEPS) {
                issue_stage(smb, (gs + 3) & 3, QTb, KTb, pf_chunk, pf_ks, soffA, soffB, dst0);
                if (++pf_ks == KSTEPS) { pf_ks = 0; ++pf_chunk; }
            }
            CP_COMMIT();
        }

        // Epilogue: top-2 update + visible-corner store from fragments.
        const int n0 = chunk * TILE_N;
#pragma unroll
        for (int mt = 0; mt < 4; ++mt)
#pragma unroll
        for (int nt = 0; nt < 4; ++nt) {
            const int nb = n0 + wn * 32 + nt * 8 + (lane & 3) * 2;
#pragma unroll
            for (int h = 0; h < 2; ++h) {
                const int s = mt * 2 + h;
#pragma unroll
                for (int j = 0; j < 2; ++j)
                    top2_ins(acc[mt][nt][h * 2 + j], nb + j, tv1[s], ti1[s], tv2[s], ti2[s]);
            }
        }
        if (visq && n0 < VIS) {
#pragma unroll
            for (int mt = 0; mt < 4; ++mt)
#pragma unroll
            for (int h = 0; h < 2; ++h) {
                const int q = q0 + wm * 64 + mt * 16 + (lane >> 2) + h * 8;
                float* row = Svis + ((size_t)(b * VIS + q)) * VIS;
#pragma unroll
                for (int nt = 0; nt < 4; ++nt) {
                    const int n = n0 + wn * 32 + nt * 8 + (lane & 3) * 2;
                    *(float2*)(row + n) = make_float2(acc[mt][nt][h * 2], acc[mt][nt][h * 2 + 1]);
                }
            }
        }
    }

    // Lane reduction: lanes sharing a row differ in bits 0-1 of lane.
#pragma unroll
    for (int s = 0; s < 8; ++s) {
#pragma unroll
        for (int off = 1; off <= 2; off <<= 1) {
            const float ov1 = __shfl_xor_sync(0xffffffffu, tv1[s], off);
            const int   oi1 = __shfl_xor_sync(0xffffffffu, ti1[s], off);
            const float ov2 = __shfl_xor_sync(0xffffffffu, tv2[s], off);
            const int   oi2 = __shfl_xor_sync(0xffffffffu, ti2[s], off);
            top2_ins(ov1, oi1, tv1[s], ti1[s], tv2[s], ti2[s]);
            top2_ins(ov2, oi2, tv1[s], ti1[s], tv2[s], ti2[s]);
        }
    }
    // Cross-warp (4 wn groups) via smem.
    float* mv1 = (float*)(smem + SM_RED);
    int*   mi1 = (int*)(smem + SM_RED + 2048);
    float* mv2 = (float*)(smem + SM_RED + 4096);
    int*   mi2 = (int*)(smem + SM_RED + 6144);
    __syncthreads();
    if ((lane & 3) == 0) {
#pragma unroll
        for (int s = 0; s < 8; ++s) {
            const int mt = s >> 1, h = s & 1;
            const int row = wm * 64 + mt * 16 + (lane >> 2) + h * 8;
            mv1[wn * 128 + row] = tv1[s];
            mi1[wn * 128 + row] = ti1[s];
            mv2[wn * 128 + row] = tv2[s];
            mi2[wn * 128 + row] = ti2[s];
        }
    }
    __syncthreads();
    if (tid < 128) {
        float v1 = mv1[tid], v2 = mv2[tid];
        int   i1 = mi1[tid], i2 = mi2[tid];
#pragma unroll
        for (int w = 1; w < 4; ++w) {
            top2_ins(mv1[w * 128 + tid], mi1[w * 128 + tid], v1, i1, v2, i2);
            top2_ins(mv2[w * 128 + tid], mi2[w * 128 + tid], v1, i1, v2, i2);
        }
        int idx = i1;
        if (v1 - v2 < GAP_TAU) {
            // Exact fp64 re-score of the two candidates from original fp32 data.
            const float* Qc = Qo + (size_t)b * CDIM * HWDIM + (q0 + tid);
            const float* Ka = Ko + (size_t)b * CDIM * HWDIM + i1;
            const float* Kb2 = Ko + (size_t)b * CDIM * HWDIM + i2;
            double e1 = 0.0, e2 = 0.0;
            for (int c = 0; c < CDIM; ++c) {
                const double qv = (double)Qc[(size_t)c * HWDIM];
                e1 += qv * (double)Ka[(size_t)c * HWDIM];
                e2 += qv * (double)Kb2[(size_t)c * HWDIM];
            }
            if (e2 > e1 || (e2 == e1 && i2 < i1)) idx = i2;
        }
        const size_t hq = (size_t)b * HWDIM + q0 + tid;
        if (hmode == 1) ((long long*)Hout)[hq] = (long long)idx;
        else            ((float*)Hout)[hq] = (float)idx;
    }
}

extern "C" void kernel_launch(void* const* d_in, const int* in_sizes, int n_in,
                              void* d_out, int out_size)
{
    const float* Q = (const float*)d_in[0];
    const float* K = (const float*)d_in[1];
    // V unused by reference outputs.

    float* Svis = (float*)d_out;
    const size_t svis_elems = (size_t)BATCH * VIS * VIS;

    int hmode;
    void* hptr;
    if (out_size == 4227072) {
        hmode = 1;
        hptr = (void*)((char*)d_out + svis_elems * sizeof(float));
    } else {
        hmode = 0;
        hptr = (void*)((float*)d_out + svis_elems);
    }

    static int attr_done = 0;
    if (!attr_done) {
        cudaFuncSetAttribute(gemm_fp16, cudaFuncAttributeMaxDynamicSharedMemorySize, SM_TOTAL);
        attr_done = 1;
    }

    split_tp<<<dim3(HWDIM / 32, CDIM / 32, 2 * BATCH), 256>>>(Q, K);
    gemm_fp16<<<dim3(HWDIM / TILE_M, BATCH), 256, SM_TOTAL>>>(Q, K, Svis, hptr, hmode);
}

// round 8
// speedup vs baseline: 1.1602x; 1.1556x over previous
#include <cuda_runtime.h>
#include <cuda_fp16.h>
#include <cstdint>

// Problem: B=4, C=256, HW=4096. S = Q^T K per batch; outputs S[:, :1024, :1024] + argmax rows.
// 3-segment fp16 split (exact to ~1e-6): S = Qhi*Khi + Qhi*Klo + Qlo*Khi.
// Argmax guarded by fp64 re-score of top-2 when gap < GAP_TAU.
#define BATCH   4
#define CDIM    256
#define HWDIM   4096
#define VIS     1024
#define KSPLIT  512            // [hi(256) | lo(256)] halfs per hw-row
#define TILE_M  128
#define TILE_N  128
#define NCHUNKS (HWDIM / TILE_N)        // 32
#define KSTEPS  24                      // 3 segs x 8 k-blocks of 32
#define TOTSTEPS (NCHUNKS * KSTEPS)     // 768
#define STAGE_BYTES 16384               // A 8KB + B 8KB
#define SM_RED  65536                   // after 4 stages
#define SM_TOTAL (SM_RED + 8192)
#define GAP_TAU 0.05f

// Scratch: transposed + fp16 hi/lo split operands (allocation-free device globals).
__device__ __half g_QT[(size_t)BATCH * HWDIM * KSPLIT];
__device__ __half g_KT[(size_t)BATCH * HWDIM * KSPLIT];

#define CP16(dst, src) \
    asm volatile("cp.async.cg.shared.global [%0], [%1], 16;" :: "r"(dst), "l"(src))
#define CP_COMMIT() asm volatile("cp.async.commit_group;" ::: "memory")
#define CP_WAIT2()  asm volatile("cp.async.wait_group 2;" ::: "memory")

__device__ __forceinline__ uint32_t smem_u32(const void* p) {
    uint32_t a;
    asm("{ .reg .u64 t; cvta.to.shared.u64 t, %1; cvt.u32.u64 %0, t; }" : "=r"(a) : "l"(p));
    return a;
}
__device__ __forceinline__ void ldsm4(uint32_t* r, uint32_t addr) {
    asm volatile("ldmatrix.sync.aligned.m8n8.x4.shared.b16 {%0,%1,%2,%3}, [%4];"
                 : "=r"(r[0]), "=r"(r[1]), "=r"(r[2]), "=r"(r[3]) : "r"(addr));
}
__device__ __forceinline__ void mma16816(float* d, const uint32_t* a, const uint32_t* b) {
    asm volatile("mma.sync.aligned.m16n8k16.row.col.f32.f16.f16.f32 "
                 "{%0,%1,%2,%3}, {%4,%5,%6,%7}, {%8,%9}, {%0,%1,%2,%3};"
                 : "+f"(d[0]), "+f"(d[1]), "+f"(d[2]), "+f"(d[3])
                 : "r"(a[0]), "r"(a[1]), "r"(a[2]), "r"(a[3]), "r"(b[0]), "r"(b[1]));
}
__device__ __forceinline__ void top2_ins(float v, int i, float& v1, int& i1, float& v2, int& i2) {
    if (v > v1 || (v == v1 && i < i1)) { v2 = v1; i2 = i1; v1 = v; i1 = i; }
    else if (v > v2 || (v == v2 && i < i2)) { v2 = v; i2 = i; }
}

// ---- Kernel 1: transpose + fp16 hi/lo split ----
__global__ __launch_bounds__(256, 4)
void split_tp(const float* __restrict__ Q, const float* __restrict__ K)
{
    const int bz = blockIdx.z;                   // bit0 = which tensor, bits1.. = batch
    const float* src = ((bz & 1) ? K : Q) + (size_t)(bz >> 1) * CDIM * HWDIM;
    __half* dst = ((bz & 1) ? g_KT : g_QT) + (size_t)(bz >> 1) * HWDIM * KSPLIT;
    __shared__ float t[32][33];
    const int x0 = blockIdx.x * 32;              // hw
    const int y0 = blockIdx.y * 32;              // c
    const int tx = threadIdx.x & 31, ty = threadIdx.x >> 5;
#pragma unroll
    for (int j = 0; j < 4; ++j)
        t[ty + 8 * j][tx] = src[(size_t)(y0 + ty + 8 * j) * HWDIM + x0 + tx];
    __syncthreads();
#pragma unroll
    for (int j = 0; j < 4; ++j) {
        const int hw = x0 + ty + 8 * j;
        const float x = t[tx][ty + 8 * j];
        const __half hi = __float2half_rn(x);
        const __half lo = __float2half_rn(x - __half2float(hi));
        const size_t o = (size_t)hw * KSPLIT + y0 + tx;
        dst[o] = hi;
        dst[o + CDIM] = lo;
    }
}

// one cp.async stage: A 128x32 halfs (8KB), B 128x32 halfs (8KB), swizzled 64B rows.
__device__ __forceinline__ void issue_stage(
    uint32_t smb, int slot, const __half* QTb, const __half* KTb,
    int chunk, int ks, int soff, int dst0)
{
    const int seg = ks >> 3, kb = ks & 7;
    const int ca = ((seg == 2) ? CDIM : 0) + kb * 32;   // A: [hi | hi | lo]
    const int cb = ((seg == 1) ? CDIM : 0) + kb * 32;   // B: [hi | lo | hi]
    const uint32_t ab = smb + slot * STAGE_BYTES;
    const uint32_t bb = ab + 8192;
    const __half* pa = QTb + soff + ca;
    CP16(ab + dst0, pa);
    CP16(ab + dst0 + 4096, pa + 64 * KSPLIT);
    const __half* pb = KTb + (size_t)chunk * TILE_N * KSPLIT + soff + cb;
    CP16(bb + dst0, pb);
    CP16(bb + dst0 + 4096, pb + 64 * KSPLIT);
}

// ---- Kernel 2: fp16-split mma.sync GEMM + top2 argmax + exact fixup ----
__global__ __launch_bounds__(256, 1)
void gemm_fp16(const float* __restrict__ Qo, const float* __restrict__ Ko,
               float* __restrict__ Svis, void* __restrict__ Hout, int hmode)
{
    extern __shared__ char smem[];
    const uint32_t smb = smem_u32(smem);
    const int tid = threadIdx.x;
    const int lane = tid & 31, wid = tid >> 5;
    const int wm = wid >> 2, wn = wid & 3;          // warp grid 2(M) x 4(N), tile 64x32
    const int b = blockIdx.y;
    const int q0 = blockIdx.x * TILE_M;

    const __half* QTb = g_QT + ((size_t)(b * HWDIM + q0)) * KSPLIT;
    const __half* KTb = g_KT + (size_t)b * HWDIM * KSPLIT;

    // cp.async mapping: thread covers unit tid and tid+256 of 512 16B-units.
    const int r0 = tid >> 2, u0 = tid & 3;
    const int soff = r0 * KSPLIT + u0 * 8;
    const int dst0 = r0 * 64 + ((u0 ^ ((r0 >> 1) & 3)) * 16);

    // ldmatrix lane geometry
    const int arow = lane & 15;
    const int auk  = (lane >> 4) & 1;
    const int brow = (lane & 7) + ((lane >> 4) & 1) * 8;
    const int buk  = (lane >> 3) & 1;

    int am[4], axor[4];
#pragma unroll
    for (int mt = 0; mt < 4; ++mt) {
        const int m = wm * 64 + mt * 16 + arow;
        am[mt] = m * 64;
        axor[mt] = (m >> 1) & 3;
    }
    int bn[2], bxor[2];
#pragma unroll
    for (int p = 0; p < 2; ++p) {
        const int n = wn * 32 + p * 16 + brow;
        bn[p] = n * 64;
        bxor[p] = (n >> 1) & 3;
    }

    const float NEG_INF = __int_as_float(0xff800000);
    float tv1[8], tv2[8];
    int   ti1[8], ti2[8];
#pragma unroll
    for (int s = 0; s < 8; ++s) { tv1[s] = NEG_INF; tv2[s] = NEG_INF; ti1[s] = 0; ti2[s] = 1; }

    // Prologue: 3 stages in flight
    int pf_chunk = 0, pf_ks = 0;
#pragma unroll
    for (int s = 0; s < 3; ++s) {
        issue_stage(smb, s, QTb, KTb, pf_chunk, pf_ks, soff, dst0);
        CP_COMMIT();
        if (++pf_ks == KSTEPS) { pf_ks = 0; ++pf_chunk; }
    }

    int gs = 0;
    const bool visq = (q0 < VIS);

    for (int chunk = 0; chunk < NCHUNKS; ++chunk) {
        float acc[4][4][4];
#pragma unroll
        for (int mt = 0; mt < 4; ++mt)
#pragma unroll
        for (int nt = 0; nt < 4; ++nt)
#pragma unroll
        for (int e = 0; e < 4; ++e) acc[mt][nt][e] = 0.f;

        for (int ks = 0; ks < KSTEPS; ++ks, ++gs) {
            CP_WAIT2();
            __syncthreads();
            // Kick next stage's async loads first so they overlap this step.
            if (gs + 3 < TOTSTEPS) {
                issue_stage(smb, (gs + 3) & 3, QTb, KTb, pf_chunk, pf_ks, soff, dst0);
                if (++pf_ks == KSTEPS) { pf_ks = 0; ++pf_chunk; }
            }
            CP_COMMIT();

            const int slot = gs & 3;
            const uint32_t ab = smb + slot * STAGE_BYTES;
            const uint32_t bb = ab + 8192;

            // Batch ALL fragment loads (both k16 halves) for max LDS pipelining.
            uint32_t af[2][4][4];
            uint32_t bf[2][2][4];
#pragma unroll
            for (int k16 = 0; k16 < 2; ++k16) {
#pragma unroll
                for (int mt = 0; mt < 4; ++mt) {
                    const int u = (k16 * 2 + auk) ^ axor[mt];
                    ldsm4(af[k16][mt], ab + am[mt] + u * 16);
                }
#pragma unroll
                for (int p = 0; p < 2; ++p) {
                    const int u = (k16 * 2 + buk) ^ bxor[p];
                    ldsm4(bf[k16][p], bb + bn[p] + u * 16);
                }
            }
            // Then issue all 32 MMAs back-to-back.
#pragma unroll
            for (int k16 = 0; k16 < 2; ++k16)
#pragma unroll
            for (int mt = 0; mt < 4; ++mt)
#pragma unroll
            for (int nt = 0; nt < 4; ++nt)
                mma16816(acc[mt][nt], af[k16][mt], &bf[k16][nt >> 1][(nt & 1) * 2]);
        }

        // Epilogue: top-2 update + visible-corner store from fragments.
        const int n0 = chunk * TILE_N;
#pragma unroll
        for (int mt = 0; mt < 4; ++mt)
#pragma unroll
        for (int nt = 0; nt < 4; ++nt) {
            const int nb = n0 + wn * 32 + nt * 8 + (lane & 3) * 2;
#pragma unroll
            for (int h = 0; h < 2; ++h) {
                const int s = mt * 2 + h;
#pragma unroll
                for (int j = 0; j < 2; ++j)
                    top2_ins(acc[mt][nt][h * 2 + j], nb + j, tv1[s], ti1[s], tv2[s], ti2[s]);
            }
        }
        if (visq && n0 < VIS) {
#pragma unroll
            for (int mt = 0; mt < 4; ++mt)
#pragma unroll
            for (int h = 0; h < 2; ++h) {
                const int q = q0 + wm * 64 + mt * 16 + (lane >> 2) + h * 8;
                float* row = Svis + ((size_t)(b * VIS + q)) * VIS;
#pragma unroll
                for (int nt = 0; nt < 4; ++nt) {
                    const int n = n0 + wn * 32 + nt * 8 + (lane & 3) * 2;
                    *(float2*)(row + n) = make_float2(acc[mt][nt][h * 2], acc[mt][nt][h * 2 + 1]);
                }
            }
        }
    }

    // Lane reduction: lanes sharing a row differ in bits 0-1 of lane.
#pragma unroll
    for (int s = 0; s < 8; ++s) {
#pragma unroll
        for (int off = 1; off <= 2; off <<= 1) {
            const float ov1 = __shfl_xor_sync(0xffffffffu, tv1[s], off);
            const int   oi1 = __shfl_xor_sync(0xffffffffu, ti1[s], off);
            const float ov2 = __shfl_xor_sync(0xffffffffu, tv2[s], off);
            const int   oi2 = __shfl_xor_sync(0xffffffffu, ti2[s], off);
            top2_ins(ov1, oi1, tv1[s], ti1[s], tv2[s], ti2[s]);
            top2_ins(ov2, oi2, tv1[s], ti1[s], tv2[s], ti2[s]);
        }
    }
    // Cross-warp (4 wn groups) via smem.
    float* mv1 = (float*)(smem + SM_RED);
    int*   mi1 = (int*)(smem + SM_RED + 2048);
    float* mv2 = (float*)(smem + SM_RED + 4096);
    int*   mi2 = (int*)(smem + SM_RED + 6144);
    __syncthreads();
    if ((lane & 3) == 0) {
#pragma unroll
        for (int s = 0; s < 8; ++s) {
            const int mt = s >> 1, h = s & 1;
            const int row = wm * 64 + mt * 16 + (lane >> 2) + h * 8;
            mv1[wn * 128 + row] = tv1[s];
            mi1[wn * 128 + row] = ti1[s];
            mv2[wn * 128 + row] = tv2[s];
            mi2[wn * 128 + row] = ti2[s];
        }
    }
    __syncthreads();
    if (tid < 128) {
        float v1 = mv1[tid], v2 = mv2[tid];
        int   i1 = mi1[tid], i2 = mi2[tid];
#pragma unroll
        for (int w = 1; w < 4; ++w) {
            top2_ins(mv1[w * 128 + tid], mi1[w * 128 + tid], v1, i1, v2, i2);
            top2_ins(mv2[w * 128 + tid], mi2[w * 128 + tid], v1, i1, v2, i2);
        }
        int idx = i1;
        if (v1 - v2 < GAP_TAU) {
            // Exact fp64 re-score of the two candidates from original fp32 data.
            const float* Qc = Qo + (size_t)b * CDIM * HWDIM + (q0 + tid);
            const float* Ka = Ko + (size_t)b * CDIM * HWDIM + i1;
            const float* Kb2 = Ko + (size_t)b * CDIM * HWDIM + i2;
            double e1 = 0.0, e2 = 0.0;
            for (int c = 0; c < CDIM; ++c) {
                const double qv = (double)Qc[(size_t)c * HWDIM];
                e1 += qv * (double)Ka[(size_t)c * HWDIM];
                e2 += qv * (double)Kb2[(size_t)c * HWDIM];
            }
            if (e2 > e1 || (e2 == e1 && i2 < i1)) idx = i2;
        }
        const size_t hq = (size_t)b * HWDIM + q0 + tid;
        if (hmode == 1) ((long long*)Hout)[hq] = (long long)idx;
        else            ((float*)Hout)[hq] = (float)idx;
    }
}

extern "C" void kernel_launch(void* const* d_in, const int* in_sizes, int n_in,
                              void* d_out, int out_size)
{
    const float* Q = (const float*)d_in[0];
    const float* K = (const float*)d_in[1];
    // V unused by reference outputs.

    float* Svis = (float*)d_out;
    const size_t svis_elems = (size_t)BATCH * VIS * VIS;

    int hmode;
    void* hptr;
    if (out_size == 4227072) {
        hmode = 1;
        hptr = (void*)((char*)d_out + svis_elems * sizeof(float));
    } else {
        hmode = 0;
        hptr = (void*)((float*)d_out + svis_elems);
    }

    static int attr_done = 0;
    if (!attr_done) {
        cudaFuncSetAttribute(gemm_fp16, cudaFuncAttributeMaxDynamicSharedMemorySize, SM_TOTAL);
        attr_done = 1;
    }

    split_tp<<<dim3(HWDIM / 32, CDIM / 32, 2 * BATCH), 256>>>(Q, K);
    gemm_fp16<<<dim3(HWDIM / TILE_M, BATCH), 256, SM_TOTAL>>>(Q, K, Svis, hptr, hmode);
}